// round 8
// baseline (speedup 1.0000x reference)
#include <cuda_runtime.h>

// loss = ||F^T F - S^T S||_F^2 * 2^-38,  F/S = [ch=64, hw=8192] channel-major.
// Fused persistent kernel, 256 blocks x 512 threads:
//   Phase 1: block computes 64x64 Gram-diff partial over 32 i's.
//            Thread tile 2a x 4b; b packed straight from LDS.128 (no movs),
//            a scalars dup'd (2 movs/matrix); f32x2 packed FMA.
//   Grid barrier (all blocks co-resident: 512 thr x 2/SM, 256 <= 296 slots).
//   Phase 2: same blocks reduce partials (fixed order), square, sum;
//            deterministic last-block final fold.

#define CH    64
#define HW    8192
#define IPB   32
#define NBLK  (HW / IPB)   // 256
#define GELEM (CH * CH)    // 4096
#define PAD   68           // row stride in floats: 272B, 16B-aligned per row

typedef unsigned long long u64;

__device__ float    g_partials[NBLK * GELEM];
__device__ float    g_bp[NBLK];
__device__ unsigned g_c1;
__device__ unsigned g_c2;

__device__ __forceinline__ u64 fma2(u64 a, u64 b, u64 c) {
    u64 d;
    asm("fma.rn.f32x2 %0, %1, %2, %3;" : "=l"(d) : "l"(a), "l"(b), "l"(c));
    return d;
}
__device__ __forceinline__ u64 dup2(float x) {
    u64 r;
    asm("mov.b64 %0, {%1, %1};" : "=l"(r) : "f"(x));
    return r;
}

__global__ void __launch_bounds__(512, 2) fused_loss_kernel(const float* __restrict__ A,
                                                            const float* __restrict__ B,
                                                            float* __restrict__ out) {
    __shared__ __align__(16) float fsh[IPB][PAD];
    __shared__ __align__(16) float ssh[IPB][PAD];
    __shared__ float red[32][16];
    __shared__ float sqs[16];
    __shared__ float wsum[16];
    __shared__ bool  last;

    const int tid = threadIdx.x;
    const int bid = blockIdx.x;

    // ---------------- Phase 1 -----------------------------------------------
    {
        const int i0 = bid * IPB;
        // Stage: thread -> channel c = tid>>3, i-group g = tid&7 (coalesced LDG.128).
        const int c = tid >> 3;
        const int g = tid & 7;
        const float4 fv = *reinterpret_cast<const float4*>(A + (size_t)c * HW + i0 + 4 * g);
        const float4 sv = *reinterpret_cast<const float4*>(B + (size_t)c * HW + i0 + 4 * g);
        {
            float fvals[4] = {fv.x, fv.y, fv.z, fv.w};
            float svals[4] = {sv.x, sv.y, sv.z, sv.w};
#pragma unroll
            for (int k = 0; k < 4; ++k) {
                fsh[4 * g + k][c] = fvals[k];
                ssh[4 * g + k][c] = svals[k];
            }
        }
        __syncthreads();

        // ty = tid>>4 -> a-pair (channels 2ty, 2ty+1); tx = tid&15 -> b-quad.
        const int ty = tid >> 4;
        const int tx = tid & 15;

        u64 accf[4], accs[4];
#pragma unroll
        for (int b = 0; b < 4; ++b) { accf[b] = 0ull; accs[b] = 0ull; }

#pragma unroll 8
        for (int ii = 0; ii < IPB; ++ii) {
            float2     fa  = *reinterpret_cast<const float2*>(&fsh[ii][2 * ty]);
            ulonglong2 fbp = *reinterpret_cast<const ulonglong2*>(&fsh[ii][4 * tx]);
            float2     sa  = *reinterpret_cast<const float2*>(&ssh[ii][2 * ty]);
            ulonglong2 sbp = *reinterpret_cast<const ulonglong2*>(&ssh[ii][4 * tx]);

            u64 fd0 = dup2(fa.x), fd1 = dup2(fa.y);
            u64 sd0 = dup2(sa.x), sd1 = dup2(sa.y);

            accf[0] = fma2(fd0, fbp.x, accf[0]);
            accf[1] = fma2(fd0, fbp.y, accf[1]);
            accf[2] = fma2(fd1, fbp.x, accf[2]);
            accf[3] = fma2(fd1, fbp.y, accf[3]);
            accs[0] = fma2(sd0, sbp.x, accs[0]);
            accs[1] = fma2(sd0, sbp.y, accs[1]);
            accs[2] = fma2(sd1, sbp.x, accs[2]);
            accs[3] = fma2(sd1, sbp.y, accs[3]);
        }

        // D = F-acc - S-acc; acc[j] holds (b-pair) for a-row j>>1.
        const u64 neg1 = dup2(-1.0f);
        u64 v0 = fma2(accs[0], neg1, accf[0]);  // (D[a0][b0], D[a0][b1])
        u64 v1 = fma2(accs[1], neg1, accf[1]);  // (D[a0][b2], D[a0][b3])
        u64 v2 = fma2(accs[2], neg1, accf[2]);  // (D[a1][b0], D[a1][b1])
        u64 v3 = fma2(accs[3], neg1, accf[3]);  // (D[a1][b2], D[a1][b3])

        float* p = g_partials + (size_t)bid * GELEM;
        float2 d0 = *reinterpret_cast<float2*>(&v0);
        float2 d1 = *reinterpret_cast<float2*>(&v1);
        float2 d2 = *reinterpret_cast<float2*>(&v2);
        float2 d3 = *reinterpret_cast<float2*>(&v3);
        *reinterpret_cast<float4*>(p + (2 * ty + 0) * CH + 4 * tx) =
            make_float4(d0.x, d0.y, d1.x, d1.y);
        *reinterpret_cast<float4*>(p + (2 * ty + 1) * CH + 4 * tx) =
            make_float4(d2.x, d2.y, d3.x, d3.y);
    }

    // ---------------- Grid barrier ------------------------------------------
    __threadfence();
    __syncthreads();
    if (tid == 0) {
        atomicAdd(&g_c1, 1u);
        volatile unsigned* vc = &g_c1;
        while (*vc < NBLK) __nanosleep(32);
    }
    __syncthreads();
    __threadfence();

    // ---------------- Phase 2 -----------------------------------------------
    {
        const int lane = tid & 15;       // Gram entry within block's 16
        const int grp  = tid >> 4;       // 0..31, each sums 8 partial blocks
        const int e    = bid * 16 + lane;

        float s = 0.0f;
#pragma unroll
        for (int k = 0; k < 8; ++k)
            s += g_partials[(size_t)(grp * 8 + k) * GELEM + e];

        red[grp][lane] = s;
        __syncthreads();
#pragma unroll
        for (int off = 16; off > 0; off >>= 1) {
            if (grp < off) red[grp][lane] += red[grp + off][lane];
            __syncthreads();
        }
        if (tid < 16) {
            float tot = red[0][tid];
            sqs[tid] = tot * tot;
        }
        __syncthreads();

        if (tid == 0) {
            float bsum = 0.0f;
#pragma unroll
            for (int k = 0; k < 16; ++k) bsum += sqs[k];
            g_bp[bid] = bsum;
            __threadfence();
            last = (atomicAdd(&g_c2, 1u) == NBLK - 1);
        }
        __syncthreads();

        if (last) {
            __threadfence();
            if (tid < 256) {
                volatile float* vb = g_bp;
                float v = vb[tid];
#pragma unroll
                for (int off = 16; off > 0; off >>= 1)
                    v += __shfl_down_sync(0xffffffffu, v, off);
                if ((tid & 31) == 0) wsum[tid >> 5] = v;
            }
            __syncthreads();
            if (tid == 0) {
                float v = 0.0f;
#pragma unroll
                for (int k = 0; k < 8; ++k) v += wsum[k];
                out[0] = v * (1.0f / 274877906944.0f);  // * 2^-38 exact
                g_c1 = 0u;
                g_c2 = 0u;
            }
        }
    }
}

extern "C" void kernel_launch(void* const* d_in, const int* in_sizes, int n_in,
                              void* d_out, int out_size) {
    const float* A = (const float*)d_in[0];
    const float* B = (const float*)d_in[1];
    float* out = (float*)d_out;

    fused_loss_kernel<<<NBLK, 512>>>(A, B, out);
}

// round 10
// speedup vs baseline: 1.0273x; 1.0273x over previous
#include <cuda_runtime.h>

// loss = ||F^T F - S^T S||_F^2 * 2^-38,  F/S = [ch=64, hw=8192] channel-major.
// Fused persistent kernel, 128 blocks x 512 threads, ONE block per SM:
//   Phase 1: block computes 64x64 Gram-diff partial over 64 i's
//            (2a x 4b thread tile, f32x2 packed FMA).
//   Grid barrier: tight, since all blocks own a whole SM (no sharing skew).
//   Phase 2: 32 Gram entries per block, fixed-order sums, square, block-sum;
//            deterministic last-block final fold.

#define CH    64
#define HW    8192
#define IPB   64
#define NBLK  (HW / IPB)   // 128
#define GELEM (CH * CH)    // 4096
#define PAD   68           // row stride: 272B, every row 16B-aligned

typedef unsigned long long u64;

__device__ float    g_partials[NBLK * GELEM];
__device__ float    g_bp[NBLK];
__device__ unsigned g_c1;
__device__ unsigned g_c2;

__device__ __forceinline__ u64 fma2(u64 a, u64 b, u64 c) {
    u64 d;
    asm("fma.rn.f32x2 %0, %1, %2, %3;" : "=l"(d) : "l"(a), "l"(b), "l"(c));
    return d;
}
__device__ __forceinline__ u64 dup2(float x) {
    u64 r;
    asm("mov.b64 %0, {%1, %1};" : "=l"(r) : "f"(x));
    return r;
}

__global__ void __launch_bounds__(512, 1) fused_loss_kernel(const float* __restrict__ A,
                                                            const float* __restrict__ B,
                                                            float* __restrict__ out) {
    __shared__ __align__(16) float fsh[IPB][PAD];
    __shared__ __align__(16) float ssh[IPB][PAD];
    __shared__ float red[16][32];
    __shared__ float wsum[16];
    __shared__ bool  last;

    const int tid = threadIdx.x;
    const int bid = blockIdx.x;

    // ---------------- Phase 1: 64x64 Gram-diff partial over 64 i's ----------
    {
        const int i0 = bid * IPB;
        const int c  = tid >> 3;        // channel 0..63
        const int g0 = tid & 7;         // i-group; thread covers g0 and g0+8

        // Front-batch all 4 LDG.128, then transpose-store.
        const float4 fv0 = *reinterpret_cast<const float4*>(A + (size_t)c * HW + i0 + 4 * g0);
        const float4 fv1 = *reinterpret_cast<const float4*>(A + (size_t)c * HW + i0 + 4 * (g0 + 8));
        const float4 sv0 = *reinterpret_cast<const float4*>(B + (size_t)c * HW + i0 + 4 * g0);
        const float4 sv1 = *reinterpret_cast<const float4*>(B + (size_t)c * HW + i0 + 4 * (g0 + 8));
        {
            float f0[4] = {fv0.x, fv0.y, fv0.z, fv0.w};
            float f1[4] = {fv1.x, fv1.y, fv1.z, fv1.w};
            float s0[4] = {sv0.x, sv0.y, sv0.z, sv0.w};
            float s1[4] = {sv1.x, sv1.y, sv1.z, sv1.w};
#pragma unroll
            for (int k = 0; k < 4; ++k) {
                fsh[4 * g0 + k][c]       = f0[k];
                fsh[4 * (g0 + 8) + k][c] = f1[k];
                ssh[4 * g0 + k][c]       = s0[k];
                ssh[4 * (g0 + 8) + k][c] = s1[k];
            }
        }
        __syncthreads();

        // ty = tid>>4 -> a-pair (channels 2ty, 2ty+1); tx = tid&15 -> b-quad.
        const int ty = tid >> 4;
        const int tx = tid & 15;

        u64 accf[4], accs[4];
#pragma unroll
        for (int b = 0; b < 4; ++b) { accf[b] = 0ull; accs[b] = 0ull; }

#pragma unroll 8
        for (int ii = 0; ii < IPB; ++ii) {
            float2     fa  = *reinterpret_cast<const float2*>(&fsh[ii][2 * ty]);
            ulonglong2 fbp = *reinterpret_cast<const ulonglong2*>(&fsh[ii][4 * tx]);
            float2     sa  = *reinterpret_cast<const float2*>(&ssh[ii][2 * ty]);
            ulonglong2 sbp = *reinterpret_cast<const ulonglong2*>(&ssh[ii][4 * tx]);

            u64 fd0 = dup2(fa.x), fd1 = dup2(fa.y);
            u64 sd0 = dup2(sa.x), sd1 = dup2(sa.y);

            accf[0] = fma2(fd0, fbp.x, accf[0]);
            accf[1] = fma2(fd0, fbp.y, accf[1]);
            accf[2] = fma2(fd1, fbp.x, accf[2]);
            accf[3] = fma2(fd1, fbp.y, accf[3]);
            accs[0] = fma2(sd0, sbp.x, accs[0]);
            accs[1] = fma2(sd0, sbp.y, accs[1]);
            accs[2] = fma2(sd1, sbp.x, accs[2]);
            accs[3] = fma2(sd1, sbp.y, accs[3]);
        }

        const u64 neg1 = dup2(-1.0f);
        u64 v0 = fma2(accs[0], neg1, accf[0]);
        u64 v1 = fma2(accs[1], neg1, accf[1]);
        u64 v2 = fma2(accs[2], neg1, accf[2]);
        u64 v3 = fma2(accs[3], neg1, accf[3]);

        float* p = g_partials + (size_t)bid * GELEM;
        float2 d0 = *reinterpret_cast<float2*>(&v0);
        float2 d1 = *reinterpret_cast<float2*>(&v1);
        float2 d2 = *reinterpret_cast<float2*>(&v2);
        float2 d3 = *reinterpret_cast<float2*>(&v3);
        *reinterpret_cast<float4*>(p + (2 * ty + 0) * CH + 4 * tx) =
            make_float4(d0.x, d0.y, d1.x, d1.y);
        *reinterpret_cast<float4*>(p + (2 * ty + 1) * CH + 4 * tx) =
            make_float4(d2.x, d2.y, d3.x, d3.y);
    }

    // ---------------- Grid barrier (128 blocks, 1 per SM) -------------------
    __threadfence();
    __syncthreads();
    if (tid == 0) {
        atomicAdd(&g_c1, 1u);
        volatile unsigned* vc = &g_c1;
        while (*vc < NBLK) __nanosleep(32);
    }
    __syncthreads();
    __threadfence();

    // ---------------- Phase 2: reduce, square, sum --------------------------
    {
        const int lane = tid & 31;        // entry within block's 32 (coalesced)
        const int grp  = tid >> 5;        // 0..15, each sums 8 partial blocks
        const int e    = bid * 32 + lane; // Gram entry 0..4095

        float s = 0.0f;
#pragma unroll
        for (int k = 0; k < 8; ++k)
            s += g_partials[(size_t)(grp * 8 + k) * GELEM + e];

        red[grp][lane] = s;
        __syncthreads();
#pragma unroll
        for (int off = 8; off > 0; off >>= 1) {
            if (grp < off) red[grp][lane] += red[grp + off][lane];
            __syncthreads();
        }

        if (tid < 32) {
            float tot = red[0][tid];
            float sq  = tot * tot;
#pragma unroll
            for (int off = 16; off > 0; off >>= 1)
                sq += __shfl_down_sync(0xffffffffu, sq, off);
            if (tid == 0) {
                g_bp[bid] = sq;
                __threadfence();
                last = (atomicAdd(&g_c2, 1u) == NBLK - 1);
            }
        }
        __syncthreads();

        if (last && tid < 32) {
            __threadfence();
            volatile float* vb = g_bp;
            float v = vb[tid] + vb[tid + 32] + vb[tid + 64] + vb[tid + 96];
#pragma unroll
            for (int off = 16; off > 0; off >>= 1)
                v += __shfl_down_sync(0xffffffffu, v, off);
            if (tid == 0) {
                out[0] = v * (1.0f / 274877906944.0f);  // * 2^-38 exact
                g_c1 = 0u;
                g_c2 = 0u;
            }
        }
    }
}

extern "C" void kernel_launch(void* const* d_in, const int* in_sizes, int n_in,
                              void* d_out, int out_size) {
    const float* A = (const float*)d_in[0];
    const float* B = (const float*)d_in[1];
    float* out = (float*)d_out;

    fused_loss_kernel<<<NBLK, 512>>>(A, B, out);
}